// round 4
// baseline (speedup 1.0000x reference)
#include <cuda_runtime.h>
#include <cuda_bf16.h>

#define NMAX 50000
#define EMAX 800000
#define ETOTMAX (EMAX + NMAX)

// Scratch (device globals: allocation-free)
__device__ float g_A[NMAX * 128];     // xl
__device__ float g_B[NMAX * 128];     // xr
__device__ float g_C[NMAX * 128];     // hidden
__device__ int   g_deg[NMAX];
__device__ int   g_row[NMAX + 1];
__device__ int   g_cursor[NMAX];
__device__ int   g_csr[ETOTMAX];      // src ids grouped by dst

// ---------------------------------------------------------------------------
// helpers
// ---------------------------------------------------------------------------
__device__ __forceinline__ unsigned long long pack2(float lo, float hi) {
    unsigned long long r;
    asm("mov.b64 %0, {%1, %2};" : "=l"(r) : "f"(lo), "f"(hi));
    return r;
}
__device__ __forceinline__ void unpack2(unsigned long long v, float& lo, float& hi) {
    asm("mov.b64 {%0, %1}, %2;" : "=f"(lo), "=f"(hi) : "l"(v));
}
__device__ __forceinline__ void fma2(unsigned long long& d, unsigned long long a,
                                     unsigned long long b) {
    asm("fma.rn.f32x2 %0, %1, %2, %0;" : "+l"(d) : "l"(a), "l"(b));
}

// ---------------------------------------------------------------------------
// Dual GEMM: out{0,1}[m,n] = A[m,:] @ W{0,1}[:,n] + b{0,1}[n];  K = N = 128
// 128x128 block tile, 256 threads, 8x8 micro-tile, packed f32x2 FMA.
// Single-buffer smem, register-staged A prefetch.
// ---------------------------------------------------------------------------
__global__ void __launch_bounds__(256, 2) gemm2_kernel(
    const float* __restrict__ A,
    const float* __restrict__ W0, const float* __restrict__ b0, float* __restrict__ out0,
    const float* __restrict__ W1, const float* __restrict__ b1, float* __restrict__ out1,
    int M)
{
    const float* W    = blockIdx.y ? W1 : W0;
    const float* bias = blockIdx.y ? b1 : b0;
    float*       out  = blockIdx.y ? out1 : out0;

    __shared__ float At[32 * 132];   // [k][row], stride 132 floats
    __shared__ float Ws[32 * 132];   // [k][col], stride 132 floats

    const int tid = threadIdx.x;
    const int m0  = blockIdx.x * 128;
    const int tx  = tid & 15;        // col group: cbase = tx*8
    const int ty  = tid >> 4;        // row group: rbase = ty*8

    // A loader: warp = 32 consecutive rows, fixed k-half -> conflict-free STS
    const int  arow = tid & 127;
    const int  ah   = (tid >> 7) * 16;         // k offset 0 or 16
    const int  grow = m0 + arow;
    const bool avalid = grow < M;
    const float* aptr = A + (long long)grow * 128 + ah;

    // W loader: 4 consecutive k rows per warp, coalesced, conflict-free STS
    const int wkr  = (tid >> 5) * 4;
    const int wcol = (tid & 31) * 4;

    unsigned long long acc[32];
#pragma unroll
    for (int i = 0; i < 32; i++) acc[i] = 0ull;

    float4 areg[4];
#pragma unroll
    for (int j = 0; j < 4; j++)
        areg[j] = avalid ? *(const float4*)(aptr + j * 4)
                         : make_float4(0.f, 0.f, 0.f, 0.f);

    for (int c = 0; c < 4; c++) {
        if (c) __syncthreads();   // previous compute done before overwrite

        // store staged A chunk (transposed)
#pragma unroll
        for (int j = 0; j < 4; j++) {
            At[(ah + j * 4 + 0) * 132 + arow] = areg[j].x;
            At[(ah + j * 4 + 1) * 132 + arow] = areg[j].y;
            At[(ah + j * 4 + 2) * 132 + arow] = areg[j].z;
            At[(ah + j * 4 + 3) * 132 + arow] = areg[j].w;
        }
        // load + store W chunk (W is small & hot in cache)
        {
            float4 wv[4];
#pragma unroll
            for (int j = 0; j < 4; j++)
                wv[j] = *(const float4*)&W[(c * 32 + wkr + j) * 128 + wcol];
#pragma unroll
            for (int j = 0; j < 4; j++)
                *(float4*)&Ws[(wkr + j) * 132 + wcol] = wv[j];
        }
        __syncthreads();

        // prefetch next A chunk into registers (latency hidden by compute)
        if (c < 3) {
#pragma unroll
            for (int j = 0; j < 4; j++)
                areg[j] = avalid ? *(const float4*)(aptr + (c + 1) * 32 + j * 4)
                                 : make_float4(0.f, 0.f, 0.f, 0.f);
        }

        const float4*     At4 = (const float4*)At;
        const ulonglong2* W2  = (const ulonglong2*)Ws;
#pragma unroll 8
        for (int k = 0; k < 32; k++) {
            float4 a0 = At4[k * 33 + ty * 2];
            float4 a1 = At4[k * 33 + ty * 2 + 1];
            ulonglong2 wa = W2[k * 33 + tx * 2];
            ulonglong2 wb = W2[k * 33 + tx * 2 + 1];
            unsigned long long w[4] = {wa.x, wa.y, wb.x, wb.y};
            float as[8] = {a0.x, a0.y, a0.z, a0.w, a1.x, a1.y, a1.z, a1.w};
#pragma unroll
            for (int i = 0; i < 8; i++) {
                unsigned long long ai = pack2(as[i], as[i]);
#pragma unroll
                for (int j = 0; j < 4; j++) fma2(acc[i * 4 + j], ai, w[j]);
            }
        }
    }

    const int cbase = tx * 8;
    float4 bb0 = *(const float4*)&bias[cbase];
    float4 bb1 = *(const float4*)&bias[cbase + 4];
    const float bs[8] = {bb0.x, bb0.y, bb0.z, bb0.w, bb1.x, bb1.y, bb1.z, bb1.w};
#pragma unroll
    for (int i = 0; i < 8; i++) {
        int row = m0 + ty * 8 + i;
        if (row < M) {
            float o[8];
#pragma unroll
            for (int j = 0; j < 4; j++) unpack2(acc[i * 4 + j], o[j * 2], o[j * 2 + 1]);
            float4 v0 = make_float4(o[0] + bs[0], o[1] + bs[1], o[2] + bs[2], o[3] + bs[3]);
            float4 v1 = make_float4(o[4] + bs[4], o[5] + bs[5], o[6] + bs[6], o[7] + bs[7]);
            *(float4*)&out[(long long)row * 128 + cbase]     = v0;
            *(float4*)&out[(long long)row * 128 + cbase + 4] = v1;
        }
    }
}

// ---------------------------------------------------------------------------
// CSR build
// ---------------------------------------------------------------------------
__global__ void __launch_bounds__(256) hist_kernel(const int* __restrict__ ei,
                                                   int* __restrict__ deg, int E, int Etot)
{
    int e = blockIdx.x * blockDim.x + threadIdx.x;
    if (e >= Etot) return;
    int d = (e < E) ? ei[E + e] : (e - E);
    atomicAdd(&deg[d], 1);
}

__global__ void __launch_bounds__(1024) scan_kernel(const int* __restrict__ deg,
                                                    int* __restrict__ row,
                                                    int* __restrict__ cursor, int Nn)
{
    __shared__ int part[1024];
    const int tid   = threadIdx.x;
    const int chunk = (Nn + 1023) / 1024;
    const int lo    = tid * chunk;
    const int hi    = min(lo + chunk, Nn);

    int sum = 0;
    for (int i = lo; i < hi; i++) sum += deg[i];
    part[tid] = sum;
    __syncthreads();

    for (int off = 1; off < 1024; off <<= 1) {
        int v = (tid >= off) ? part[tid - off] : 0;
        __syncthreads();
        part[tid] += v;
        __syncthreads();
    }

    int base = (tid > 0) ? part[tid - 1] : 0;
    for (int i = lo; i < hi; i++) {
        row[i] = base;
        cursor[i] = base;
        base += deg[i];
    }
    if (tid == 1023) row[Nn] = part[1023];
}

__global__ void __launch_bounds__(256) scatter_kernel(const int* __restrict__ ei,
                                                      int* __restrict__ cursor,
                                                      int* __restrict__ csr, int E, int Etot)
{
    int e = blockIdx.x * blockDim.x + threadIdx.x;
    if (e >= Etot) return;
    int s, d;
    if (e < E) { s = ei[e]; d = ei[E + e]; }
    else       { s = e - E; d = s; }
    int pos = atomicAdd(&cursor[d], 1);
    csr[pos] = s;
}

// ---------------------------------------------------------------------------
// Node-parallel fused GATv2 aggregation. One warp per dst node.
// ---------------------------------------------------------------------------
template<int H, bool RELU>
__global__ void __launch_bounds__(256) node_agg_kernel(
    const float* __restrict__ xl, const float* __restrict__ xr,
    const int* __restrict__ row, const int* __restrict__ csr,
    const float* __restrict__ att, const float* __restrict__ bias,
    float* __restrict__ out, int Nn)
{
    int n = (blockIdx.x * blockDim.x + threadIdx.x) >> 5;
    if (n >= Nn) return;
    const int lane = threadIdx.x & 31;

    const float4 b  = ((const float4*)xr)[n * 32 + lane];
    const float4 at = ((const float4*)att)[lane];
    const float4* __restrict__ xl4 = (const float4*)xl;

    const int beg = row[n];
    const int end = row[n + 1];

    float4 acc = make_float4(0.f, 0.f, 0.f, 0.f);
    float  den = 0.f;

    // depth-2 software pipeline (deg >= 1 guaranteed by self-loop)
    float4 a0 = xl4[csr[beg] * 32 + lane];
    float4 a1 = (beg + 1 < end) ? xl4[csr[beg + 1] * 32 + lane] : a0;

    for (int i = beg; i < end; i++) {
        float4 ac = a0;
        a0 = a1;
        if (i + 2 < end) a1 = xl4[csr[i + 2] * 32 + lane];

        float sx = ac.x + b.x, sy = ac.y + b.y, sz = ac.z + b.z, sw = ac.w + b.w;
        float p;
        p = fmaxf(sx, 0.2f * sx) * at.x;
        p = fmaf(fmaxf(sy, 0.2f * sy), at.y, p);
        p = fmaf(fmaxf(sz, 0.2f * sz), at.z, p);
        p = fmaf(fmaxf(sw, 0.2f * sw), at.w, p);

        p += __shfl_xor_sync(0xffffffffu, p, 1);
        p += __shfl_xor_sync(0xffffffffu, p, 2);
        p += __shfl_xor_sync(0xffffffffu, p, 4);
        if (H == 1) {
            p += __shfl_xor_sync(0xffffffffu, p, 8);
            p += __shfl_xor_sync(0xffffffffu, p, 16);
        }
        float ex = __expf(p);
        den  += ex;
        acc.x = fmaf(ac.x, ex, acc.x);
        acc.y = fmaf(ac.y, ex, acc.y);
        acc.z = fmaf(ac.z, ex, acc.z);
        acc.w = fmaf(ac.w, ex, acc.w);
    }

    const float r  = 1.0f / (den + 1e-16f);
    const float4 bb = ((const float4*)bias)[lane];
    float4 v;
    v.x = fmaf(acc.x, r, bb.x);
    v.y = fmaf(acc.y, r, bb.y);
    v.z = fmaf(acc.z, r, bb.z);
    v.w = fmaf(acc.w, r, bb.w);
    if (RELU) {
        v.x = fmaxf(v.x, 0.f); v.y = fmaxf(v.y, 0.f);
        v.z = fmaxf(v.z, 0.f); v.w = fmaxf(v.w, 0.f);
    }
    ((float4*)out)[n * 32 + lane] = v;
}

// ---------------------------------------------------------------------------
// launch
// ---------------------------------------------------------------------------
extern "C" void kernel_launch(void* const* d_in, const int* in_sizes, int n_in,
                              void* d_out, int out_size)
{
    const int*   ei    = (const int*)d_in[0];
    const float* embed = (const float*)d_in[1];
    const float* Wl1   = (const float*)d_in[2];
    const float* bl1   = (const float*)d_in[3];
    const float* Wr1   = (const float*)d_in[4];
    const float* br1   = (const float*)d_in[5];
    const float* att1  = (const float*)d_in[6];
    const float* b1    = (const float*)d_in[7];
    const float* Wl2   = (const float*)d_in[8];
    const float* bl2   = (const float*)d_in[9];
    const float* Wr2   = (const float*)d_in[10];
    const float* br2   = (const float*)d_in[11];
    const float* att2  = (const float*)d_in[12];
    const float* b2    = (const float*)d_in[13];
    float* out = (float*)d_out;

    const int E    = in_sizes[0] / 2;
    const int Nn   = in_sizes[1] / 128;
    const int Etot = E + Nn;

    float *A, *B, *C;
    int *deg, *row, *cursor, *csr;
    cudaGetSymbolAddress((void**)&A,      g_A);
    cudaGetSymbolAddress((void**)&B,      g_B);
    cudaGetSymbolAddress((void**)&C,      g_C);
    cudaGetSymbolAddress((void**)&deg,    g_deg);
    cudaGetSymbolAddress((void**)&row,    g_row);
    cudaGetSymbolAddress((void**)&cursor, g_cursor);
    cudaGetSymbolAddress((void**)&csr,    g_csr);

    const dim3 gemm_grid((Nn + 127) / 128, 2);
    const int  ethr_blocks  = (Etot + 255) / 256;
    const int  nwarp_blocks = (Nn * 32 + 255) / 256;

    // ---- CSR build (shared by both layers) ----
    cudaMemsetAsync(deg, 0, Nn * sizeof(int));
    hist_kernel<<<ethr_blocks, 256>>>(ei, deg, E, Etot);
    scan_kernel<<<1, 1024>>>(deg, row, cursor, Nn);
    scatter_kernel<<<ethr_blocks, 256>>>(ei, cursor, csr, E, Etot);

    // ---- layer 1 (4 heads x 32 ch) ----
    gemm2_kernel<<<gemm_grid, 256>>>(embed, Wl1, bl1, A, Wr1, br1, B, Nn);
    node_agg_kernel<4, true><<<nwarp_blocks, 256>>>(A, B, row, csr, att1, b1, C, Nn);

    // ---- layer 2 (1 head x 128 ch) ----
    gemm2_kernel<<<gemm_grid, 256>>>(C, Wl2, bl2, A, Wr2, br2, B, Nn);
    node_agg_kernel<1, false><<<nwarp_blocks, 256>>>(A, B, row, csr, att2, b2, out, Nn);
}

// round 6
// speedup vs baseline: 1.0026x; 1.0026x over previous
#include <cuda_runtime.h>
#include <cuda_bf16.h>
#include <cstdint>

#define NMAX 50000
#define EMAX 800000
#define ETOTMAX (EMAX + NMAX)

// Scratch (device globals: allocation-free)
__device__ float g_A[NMAX * 128];               // xl
__device__ float g_B[NMAX * 128];               // xr
__device__ float g_C[NMAX * 128];               // hidden
__device__ __nv_bfloat16 g_Ah[NMAX * 128];      // bf16 hi split of GEMM input
__device__ __nv_bfloat16 g_Al[NMAX * 128];      // bf16 lo split
__device__ __nv_bfloat16 g_Wth[2 * 128 * 128];  // W^T hi (tile0 = Wl, tile1 = Wr), [n][k]
__device__ __nv_bfloat16 g_Wtl[2 * 128 * 128];  // W^T lo
__device__ int g_deg[NMAX];
__device__ int g_row[NMAX + 1];
__device__ int g_cursor[NMAX];
__device__ int g_csr[ETOTMAX];

// ---------------------------------------------------------------------------
// helpers
// ---------------------------------------------------------------------------
__device__ __forceinline__ uint32_t smem_u32(const void* p) {
    uint32_t a;
    asm("{ .reg .u64 t; cvta.to.shared.u64 t, %1; cvt.u32.u64 %0, t; }" : "=r"(a) : "l"(p));
    return a;
}
__device__ __forceinline__ void ldsm_x4(uint32_t& r0, uint32_t& r1, uint32_t& r2,
                                        uint32_t& r3, uint32_t addr) {
    asm volatile("ldmatrix.sync.aligned.m8n8.x4.shared.b16 {%0,%1,%2,%3}, [%4];"
                 : "=r"(r0), "=r"(r1), "=r"(r2), "=r"(r3) : "r"(addr));
}
__device__ __forceinline__ void mma_bf16(float& d0, float& d1, float& d2, float& d3,
                                         uint32_t a0, uint32_t a1, uint32_t a2, uint32_t a3,
                                         uint32_t b0, uint32_t b1) {
    asm volatile(
        "mma.sync.aligned.m16n8k16.row.col.f32.bf16.bf16.f32 "
        "{%0,%1,%2,%3}, {%4,%5,%6,%7}, {%8,%9}, {%0,%1,%2,%3};"
        : "+f"(d0), "+f"(d1), "+f"(d2), "+f"(d3)
        : "r"(a0), "r"(a1), "r"(a2), "r"(a3), "r"(b0), "r"(b1));
}

// ---------------------------------------------------------------------------
// bf16 hi/lo split of a f32 matrix (row-major [*,128])
// ---------------------------------------------------------------------------
__global__ void __launch_bounds__(256) split_kernel(
    const float4* __restrict__ src, __nv_bfloat162* __restrict__ hi,
    __nv_bfloat162* __restrict__ lo, int n4)
{
    int i = blockIdx.x * blockDim.x + threadIdx.x;
    if (i >= n4) return;
    float4 v = src[i];
    __nv_bfloat16 h0 = __float2bfloat16(v.x), h1 = __float2bfloat16(v.y);
    __nv_bfloat16 h2 = __float2bfloat16(v.z), h3 = __float2bfloat16(v.w);
    __nv_bfloat16 l0 = __float2bfloat16(v.x - __bfloat162float(h0));
    __nv_bfloat16 l1 = __float2bfloat16(v.y - __bfloat162float(h1));
    __nv_bfloat16 l2 = __float2bfloat16(v.z - __bfloat162float(h2));
    __nv_bfloat16 l3 = __float2bfloat16(v.w - __bfloat162float(h3));
    hi[i * 2 + 0] = __halves2bfloat162(h0, h1);
    hi[i * 2 + 1] = __halves2bfloat162(h2, h3);
    lo[i * 2 + 0] = __halves2bfloat162(l0, l1);
    lo[i * 2 + 1] = __halves2bfloat162(l2, l3);
}

// transpose + split W[k][n] -> Wt_hi/lo[n][k]   (blockIdx.y selects W0/W1)
__global__ void __launch_bounds__(256) splitW_kernel(
    const float* __restrict__ W0, const float* __restrict__ W1,
    __nv_bfloat16* __restrict__ Wth, __nv_bfloat16* __restrict__ Wtl)
{
    const float* W = blockIdx.y ? W1 : W0;
    __nv_bfloat16* th = Wth + blockIdx.y * 16384;
    __nv_bfloat16* tl = Wtl + blockIdx.y * 16384;
    for (int i = threadIdx.x; i < 16384; i += 256) {
        int k = i >> 7, n = i & 127;
        float v = W[k * 128 + n];
        __nv_bfloat16 h = __float2bfloat16(v);
        th[n * 128 + k] = h;
        tl[n * 128 + k] = __float2bfloat16(v - __bfloat162float(h));
    }
}

// ---------------------------------------------------------------------------
// Tensor-core dual GEMM via mma.sync (bf16x3 split, fp32 acc):
//   out = A @ W + bias, W selected by blockIdx.y.
// Block: 128 rows x 128 cols, 256 threads (8 warps), warp = 16 rows x 128 cols.
// Smem: full A(hi,lo) + Wt(hi,lo) tiles, 272B row pitch (ldmatrix conflict-free).
// ---------------------------------------------------------------------------
#define PITCH   272          // bytes per 128-bf16 row (16B pad)
#define SM_AH   0
#define SM_AL   (128 * PITCH)
#define SM_WH   (2 * 128 * PITCH)
#define SM_WL   (3 * 128 * PITCH)
#define SM_MMA_TOTAL (4 * 128 * PITCH)   // 139264 B

__global__ void __launch_bounds__(256) mma_gemm_kernel(
    const __nv_bfloat16* __restrict__ Ah, const __nv_bfloat16* __restrict__ Al,
    const __nv_bfloat16* __restrict__ Wth, const __nv_bfloat16* __restrict__ Wtl,
    const float* __restrict__ b0, const float* __restrict__ b1,
    float* __restrict__ out0, float* __restrict__ out1, int M)
{
    extern __shared__ char smem[];
    const int tid  = threadIdx.x;
    const int wid  = tid >> 5;
    const int lane = tid & 31;
    const int m0   = blockIdx.x * 128;

    const __nv_bfloat16* WH = Wth + blockIdx.y * 16384;
    const __nv_bfloat16* WL = Wtl + blockIdx.y * 16384;
    const float* bias = blockIdx.y ? b1 : b0;
    float*       out  = blockIdx.y ? out1 : out0;

    // ---- stage tiles: 16B chunk per thread-iteration ----
    // A tiles: row r (may exceed M -> zero), 16 chunks of 16B per row
    for (int i = tid; i < 2048; i += 256) {
        int r = i >> 4, c = i & 15;
        uint4 vh = make_uint4(0u, 0u, 0u, 0u), vl = vh;
        if (m0 + r < M) {
            vh = *(const uint4*)(Ah + (size_t)(m0 + r) * 128 + c * 8);
            vl = *(const uint4*)(Al + (size_t)(m0 + r) * 128 + c * 8);
        }
        *(uint4*)(smem + SM_AH + r * PITCH + c * 16) = vh;
        *(uint4*)(smem + SM_AL + r * PITCH + c * 16) = vl;
    }
    for (int i = tid; i < 2048; i += 256) {
        int r = i >> 4, c = i & 15;
        *(uint4*)(smem + SM_WH + r * PITCH + c * 16) =
            *(const uint4*)(WH + (size_t)r * 128 + c * 8);
        *(uint4*)(smem + SM_WL + r * PITCH + c * 16) =
            *(const uint4*)(WL + (size_t)r * 128 + c * 8);
    }
    __syncthreads();

    const uint32_t sb   = smem_u32(smem);
    const int      wrow = wid * 16;

    // ldmatrix source addresses for this lane
    // A: row = wrow + (lane&15), byte koff = (lane>>4)*16  (+ q*32 per chunk)
    const uint32_t a_base = sb + (wrow + (lane & 15)) * PITCH + (lane >> 4) * 16;
    // B: covering n-pair p (n-tiles 2p,2p+1):
    //   g = lane>>3; nrow = 16p + (g>>1)*8 + (lane&7); koff = (g&1)*16
    const int      g      = lane >> 3;
    const uint32_t b_base = sb + ((g >> 1) * 8 + (lane & 7)) * PITCH + (g & 1) * 16;

    float acc[16][4];
#pragma unroll
    for (int t = 0; t < 16; t++)
#pragma unroll
        for (int j = 0; j < 4; j++) acc[t][j] = 0.f;

#pragma unroll
    for (int q = 0; q < 8; q++) {
        const uint32_t koff = q * 32;
        uint32_t ah0, ah1, ah2, ah3, al0, al1, al2, al3;
        ldsm_x4(ah0, ah1, ah2, ah3, a_base + SM_AH + koff);
        ldsm_x4(al0, al1, al2, al3, a_base + SM_AL + koff);

#pragma unroll
        for (int p = 0; p < 8; p++) {
            const uint32_t bb = b_base + p * (16 * PITCH) + koff;
            uint32_t w0, w1, w2, w3;
            // Wh: Ah@Wh and Al@Wh
            ldsm_x4(w0, w1, w2, w3, bb + SM_WH);
            mma_bf16(acc[2*p][0],   acc[2*p][1],   acc[2*p][2],   acc[2*p][3],
                     ah0, ah1, ah2, ah3, w0, w1);
            mma_bf16(acc[2*p+1][0], acc[2*p+1][1], acc[2*p+1][2], acc[2*p+1][3],
                     ah0, ah1, ah2, ah3, w2, w3);
            mma_bf16(acc[2*p][0],   acc[2*p][1],   acc[2*p][2],   acc[2*p][3],
                     al0, al1, al2, al3, w0, w1);
            mma_bf16(acc[2*p+1][0], acc[2*p+1][1], acc[2*p+1][2], acc[2*p+1][3],
                     al0, al1, al2, al3, w2, w3);
            // Wl: Ah@Wl
            ldsm_x4(w0, w1, w2, w3, bb + SM_WL);
            mma_bf16(acc[2*p][0],   acc[2*p][1],   acc[2*p][2],   acc[2*p][3],
                     ah0, ah1, ah2, ah3, w0, w1);
            mma_bf16(acc[2*p+1][0], acc[2*p+1][1], acc[2*p+1][2], acc[2*p+1][3],
                     ah0, ah1, ah2, ah3, w2, w3);
        }
    }

    // ---- epilogue: acc[t] = {(r0,c),(r0,c+1),(r1,c),(r1,c+1)}, c = t*8+(lane&3)*2
    const int r0 = m0 + wrow + (lane >> 2);
    const int r1 = r0 + 8;
#pragma unroll
    for (int t = 0; t < 16; t++) {
        const int c = t * 8 + (lane & 3) * 2;
        const float bx = bias[c], by = bias[c + 1];
        if (r0 < M) {
            float2 v = make_float2(acc[t][0] + bx, acc[t][1] + by);
            *(float2*)&out[(size_t)r0 * 128 + c] = v;
        }
        if (r1 < M) {
            float2 v = make_float2(acc[t][2] + bx, acc[t][3] + by);
            *(float2*)&out[(size_t)r1 * 128 + c] = v;
        }
    }
}

// ---------------------------------------------------------------------------
// CSR build
// ---------------------------------------------------------------------------
__global__ void __launch_bounds__(256) hist_kernel(const int* __restrict__ ei,
                                                   int* __restrict__ deg, int E, int Etot)
{
    int e = blockIdx.x * blockDim.x + threadIdx.x;
    if (e >= Etot) return;
    int d = (e < E) ? ei[E + e] : (e - E);
    atomicAdd(&deg[d], 1);
}

__global__ void __launch_bounds__(1024) scan_kernel(const int* __restrict__ deg,
                                                    int* __restrict__ row,
                                                    int* __restrict__ cursor, int Nn)
{
    __shared__ int part[1024];
    const int tid   = threadIdx.x;
    const int chunk = (Nn + 1023) / 1024;
    const int lo    = tid * chunk;
    const int hi    = min(lo + chunk, Nn);

    int sum = 0;
    for (int i = lo; i < hi; i++) sum += deg[i];
    part[tid] = sum;
    __syncthreads();

    for (int off = 1; off < 1024; off <<= 1) {
        int v = (tid >= off) ? part[tid - off] : 0;
        __syncthreads();
        part[tid] += v;
        __syncthreads();
    }

    int base = (tid > 0) ? part[tid - 1] : 0;
    for (int i = lo; i < hi; i++) {
        row[i] = base;
        cursor[i] = base;
        base += deg[i];
    }
    if (tid == 1023) row[Nn] = part[1023];
}

__global__ void __launch_bounds__(256) scatter_kernel(const int* __restrict__ ei,
                                                      int* __restrict__ cursor,
                                                      int* __restrict__ csr, int E, int Etot)
{
    int e = blockIdx.x * blockDim.x + threadIdx.x;
    if (e >= Etot) return;
    int s, d;
    if (e < E) { s = ei[e]; d = ei[E + e]; }
    else       { s = e - E; d = s; }
    int pos = atomicAdd(&cursor[d], 1);
    csr[pos] = s;
}

// ---------------------------------------------------------------------------
// Node-parallel fused GATv2 aggregation. One warp per dst node.  (R3 version)
// ---------------------------------------------------------------------------
__device__ __forceinline__ float lrelu(float x) { return x > 0.0f ? x : 0.2f * x; }

template<int H, bool RELU>
__global__ void __launch_bounds__(256) node_agg_kernel(
    const float* __restrict__ xl, const float* __restrict__ xr,
    const int* __restrict__ row, const int* __restrict__ csr,
    const float* __restrict__ att, const float* __restrict__ bias,
    float* __restrict__ out, int Nn)
{
    int n = (blockIdx.x * blockDim.x + threadIdx.x) >> 5;
    if (n >= Nn) return;
    const int lane = threadIdx.x & 31;

    const float4 b  = ((const float4*)xr)[n * 32 + lane];
    const float4 at = ((const float4*)att)[lane];

    const int beg = row[n];
    const int end = row[n + 1];

    float4 acc = make_float4(0.f, 0.f, 0.f, 0.f);
    float  den = 0.f;

    float4 a = ((const float4*)xl)[csr[beg] * 32 + lane];
    for (int i = beg; i < end; i++) {
        float4 ac = a;
        if (i + 1 < end) a = ((const float4*)xl)[csr[i + 1] * 32 + lane];

        float p = lrelu(ac.x + b.x) * at.x
                + lrelu(ac.y + b.y) * at.y
                + lrelu(ac.z + b.z) * at.z
                + lrelu(ac.w + b.w) * at.w;
        p += __shfl_xor_sync(0xffffffffu, p, 1);
        p += __shfl_xor_sync(0xffffffffu, p, 2);
        p += __shfl_xor_sync(0xffffffffu, p, 4);
        if (H == 1) {
            p += __shfl_xor_sync(0xffffffffu, p, 8);
            p += __shfl_xor_sync(0xffffffffu, p, 16);
        }
        float ex = __expf(p);
        den  += ex;
        acc.x = fmaf(ac.x, ex, acc.x);
        acc.y = fmaf(ac.y, ex, acc.y);
        acc.z = fmaf(ac.z, ex, acc.z);
        acc.w = fmaf(ac.w, ex, acc.w);
    }

    const float r  = 1.0f / (den + 1e-16f);
    const float4 bb = ((const float4*)bias)[lane];
    float4 v;
    v.x = fmaf(acc.x, r, bb.x);
    v.y = fmaf(acc.y, r, bb.y);
    v.z = fmaf(acc.z, r, bb.z);
    v.w = fmaf(acc.w, r, bb.w);
    if (RELU) {
        v.x = fmaxf(v.x, 0.f); v.y = fmaxf(v.y, 0.f);
        v.z = fmaxf(v.z, 0.f); v.w = fmaxf(v.w, 0.f);
    }
    ((float4*)out)[n * 32 + lane] = v;
}

// ---------------------------------------------------------------------------
// launch
// ---------------------------------------------------------------------------
extern "C" void kernel_launch(void* const* d_in, const int* in_sizes, int n_in,
                              void* d_out, int out_size)
{
    const int*   ei    = (const int*)d_in[0];
    const float* embed = (const float*)d_in[1];
    const float* Wl1   = (const float*)d_in[2];
    const float* bl1   = (const float*)d_in[3];
    const float* Wr1   = (const float*)d_in[4];
    const float* br1   = (const float*)d_in[5];
    const float* att1  = (const float*)d_in[6];
    const float* b1    = (const float*)d_in[7];
    const float* Wl2   = (const float*)d_in[8];
    const float* bl2   = (const float*)d_in[9];
    const float* Wr2   = (const float*)d_in[10];
    const float* br2   = (const float*)d_in[11];
    const float* att2  = (const float*)d_in[12];
    const float* b2    = (const float*)d_in[13];
    float* out = (float*)d_out;

    const int E    = in_sizes[0] / 2;
    const int Nn   = in_sizes[1] / 128;
    const int Etot = E + Nn;

    float *A, *B, *C;
    __nv_bfloat16 *Ah, *Al, *Wth, *Wtl;
    int *deg, *row, *cursor, *csr;
    cudaGetSymbolAddress((void**)&A,      g_A);
    cudaGetSymbolAddress((void**)&B,      g_B);
    cudaGetSymbolAddress((void**)&C,      g_C);
    cudaGetSymbolAddress((void**)&Ah,     g_Ah);
    cudaGetSymbolAddress((void**)&Al,     g_Al);
    cudaGetSymbolAddress((void**)&Wth,    g_Wth);
    cudaGetSymbolAddress((void**)&Wtl,    g_Wtl);
    cudaGetSymbolAddress((void**)&deg,    g_deg);
    cudaGetSymbolAddress((void**)&row,    g_row);
    cudaGetSymbolAddress((void**)&cursor, g_cursor);
    cudaGetSymbolAddress((void**)&csr,    g_csr);

    cudaFuncSetAttribute(mma_gemm_kernel,
                         cudaFuncAttributeMaxDynamicSharedMemorySize, SM_MMA_TOTAL);

    const int  ethr_blocks  = (Etot + 255) / 256;
    const int  nwarp_blocks = (Nn * 32 + 255) / 256;
    const int  split_blocks = (Nn * 32 + 255) / 256;
    const dim3 mma_grid((Nn + 127) / 128, 2);
    const dim3 wgrid(1, 2);

    // ---- CSR build (shared by both layers) ----
    cudaMemsetAsync(deg, 0, Nn * sizeof(int));
    hist_kernel<<<ethr_blocks, 256>>>(ei, deg, E, Etot);
    scan_kernel<<<1, 1024>>>(deg, row, cursor, Nn);
    scatter_kernel<<<ethr_blocks, 256>>>(ei, cursor, csr, E, Etot);

    // ---- layer 1 (4 heads x 32 ch) ----
    split_kernel<<<split_blocks, 256>>>((const float4*)embed,
                                        (__nv_bfloat162*)Ah, (__nv_bfloat162*)Al, Nn * 32);
    splitW_kernel<<<wgrid, 256>>>(Wl1, Wr1, Wth, Wtl);
    mma_gemm_kernel<<<mma_grid, 256, SM_MMA_TOTAL>>>(Ah, Al, Wth, Wtl, bl1, br1, A, B, Nn);
    node_agg_kernel<4, true><<<nwarp_blocks, 256>>>(A, B, row, csr, att1, b1, C, Nn);

    // ---- layer 2 (1 head x 128 ch) ----
    split_kernel<<<split_blocks, 256>>>((const float4*)C,
                                        (__nv_bfloat162*)Ah, (__nv_bfloat162*)Al, Nn * 32);
    splitW_kernel<<<wgrid, 256>>>(Wl2, Wr2, Wth, Wtl);
    mma_gemm_kernel<<<mma_grid, 256, SM_MMA_TOTAL>>>(Ah, Al, Wth, Wtl, bl2, br2, A, B, Nn);
    node_agg_kernel<1, false><<<nwarp_blocks, 256>>>(A, B, row, csr, att2, b2, out, Nn);
}

// round 7
// speedup vs baseline: 1.1095x; 1.1066x over previous
#include <cuda_runtime.h>
#include <cuda_bf16.h>

#define NMAX 50000
#define EMAX 800000
#define ETOTMAX (EMAX + NMAX)

// Scratch (device globals: allocation-free)
__device__ float g_A[NMAX * 128];     // xl
__device__ float g_B[NMAX * 128];     // xr
__device__ float g_C[NMAX * 128];     // hidden
__device__ int   g_deg[NMAX];
__device__ int   g_row[NMAX + 1];
__device__ int   g_cursor[NMAX];
__device__ int   g_csr[ETOTMAX];      // src ids grouped by dst

// ---------------------------------------------------------------------------
// helpers
// ---------------------------------------------------------------------------
__device__ __forceinline__ unsigned long long pack2(float lo, float hi) {
    unsigned long long r;
    asm("mov.b64 %0, {%1, %2};" : "=l"(r) : "f"(lo), "f"(hi));
    return r;
}
__device__ __forceinline__ void unpack2(unsigned long long v, float& lo, float& hi) {
    asm("mov.b64 {%0, %1}, %2;" : "=f"(lo), "=f"(hi) : "l"(v));
}
__device__ __forceinline__ void fma2(unsigned long long& d, unsigned long long a,
                                     unsigned long long b) {
    asm("fma.rn.f32x2 %0, %1, %2, %0;" : "+l"(d) : "l"(a), "l"(b));
}

// ---------------------------------------------------------------------------
// Dual GEMM (R3 version, measured 78.7us): out = A @ W{0,1} + b{0,1}
// 64x128 tile, 256 threads, 4x8 micro-tile, packed f32x2 FMA.
// ---------------------------------------------------------------------------
__global__ void __launch_bounds__(256) gemm2_kernel(
    const float* __restrict__ A,
    const float* __restrict__ W0, const float* __restrict__ b0, float* __restrict__ out0,
    const float* __restrict__ W1, const float* __restrict__ b1, float* __restrict__ out1,
    int M)
{
    const float* W    = blockIdx.y ? W1 : W0;
    const float* bias = blockIdx.y ? b1 : b0;
    float*       out  = blockIdx.y ? out1 : out0;

    __shared__ float Ws[16 * 128];
    __shared__ float At[16 * 68];

    const int tid   = threadIdx.x;
    const int m0    = blockIdx.x * 64;
    const int rbase = (tid & 15) << 2;
    const int cbase = (tid >> 4) << 3;

    unsigned long long acc2[16];
#pragma unroll
    for (int i = 0; i < 16; i++) acc2[i] = 0ull;

    const int  r_ld   = tid >> 2;
    const int  q_ld   = tid & 3;
    const bool rvalid = (m0 + r_ld) < M;

    for (int kk = 0; kk < 128; kk += 16) {
        float4 av = make_float4(0.f, 0.f, 0.f, 0.f);
        if (rvalid) av = *(const float4*)&A[(m0 + r_ld) * 128 + kk + q_ld * 4];
        float4 wv0 = *(const float4*)&W[kk * 128 + tid * 4];
        float4 wv1 = *(const float4*)&W[kk * 128 + 1024 + tid * 4];

        __syncthreads();
        At[(q_ld * 4 + 0) * 68 + r_ld] = av.x;
        At[(q_ld * 4 + 1) * 68 + r_ld] = av.y;
        At[(q_ld * 4 + 2) * 68 + r_ld] = av.z;
        At[(q_ld * 4 + 3) * 68 + r_ld] = av.w;
        *(float4*)&Ws[tid * 4]        = wv0;
        *(float4*)&Ws[1024 + tid * 4] = wv1;
        __syncthreads();

#pragma unroll
        for (int k = 0; k < 16; k++) {
            float4 a = *(const float4*)&At[k * 68 + rbase];
            ulonglong2 w0 = *(const ulonglong2*)&Ws[k * 128 + cbase];
            ulonglong2 w1 = *(const ulonglong2*)&Ws[k * 128 + cbase + 4];
            unsigned long long wv[4] = {w0.x, w0.y, w1.x, w1.y};
            unsigned long long a2[4];
            a2[0] = pack2(a.x, a.x);
            a2[1] = pack2(a.y, a.y);
            a2[2] = pack2(a.z, a.z);
            a2[3] = pack2(a.w, a.w);
#pragma unroll
            for (int i = 0; i < 4; i++)
#pragma unroll
                for (int j = 0; j < 4; j++)
                    fma2(acc2[i * 4 + j], a2[i], wv[j]);
        }
    }

    float4 bb0 = *(const float4*)&bias[cbase];
    float4 bb1 = *(const float4*)&bias[cbase + 4];
    const float bs[8] = {bb0.x, bb0.y, bb0.z, bb0.w, bb1.x, bb1.y, bb1.z, bb1.w};
#pragma unroll
    for (int i = 0; i < 4; i++) {
        int row = m0 + rbase + i;
        if (row < M) {
            float o[8];
#pragma unroll
            for (int j = 0; j < 4; j++) unpack2(acc2[i * 4 + j], o[j * 2], o[j * 2 + 1]);
            float4 v0 = make_float4(o[0] + bs[0], o[1] + bs[1], o[2] + bs[2], o[3] + bs[3]);
            float4 v1 = make_float4(o[4] + bs[4], o[5] + bs[5], o[6] + bs[6], o[7] + bs[7]);
            *(float4*)&out[row * 128 + cbase]     = v0;
            *(float4*)&out[row * 128 + cbase + 4] = v1;
        }
    }
}

// ---------------------------------------------------------------------------
// CSR build
// ---------------------------------------------------------------------------
__global__ void __launch_bounds__(256) hist_kernel(const int* __restrict__ ei,
                                                   int* __restrict__ deg, int E, int Etot)
{
    int e = blockIdx.x * blockDim.x + threadIdx.x;
    if (e >= Etot) return;
    int d = (e < E) ? ei[E + e] : (e - E);
    atomicAdd(&deg[d], 1);
}

__global__ void __launch_bounds__(1024) scan_kernel(const int* __restrict__ deg,
                                                    int* __restrict__ row,
                                                    int* __restrict__ cursor, int Nn)
{
    __shared__ int part[1024];
    const int tid   = threadIdx.x;
    const int chunk = (Nn + 1023) / 1024;
    const int lo    = tid * chunk;
    const int hi    = min(lo + chunk, Nn);

    int sum = 0;
    for (int i = lo; i < hi; i++) sum += deg[i];
    part[tid] = sum;
    __syncthreads();

    for (int off = 1; off < 1024; off <<= 1) {
        int v = (tid >= off) ? part[tid - off] : 0;
        __syncthreads();
        part[tid] += v;
        __syncthreads();
    }

    int base = (tid > 0) ? part[tid - 1] : 0;
    for (int i = lo; i < hi; i++) {
        row[i] = base;
        cursor[i] = base;
        base += deg[i];
    }
    if (tid == 1023) row[Nn] = part[1023];
}

__global__ void __launch_bounds__(256) scatter_kernel(const int* __restrict__ ei,
                                                      int* __restrict__ cursor,
                                                      int* __restrict__ csr, int E, int Etot)
{
    int e = blockIdx.x * blockDim.x + threadIdx.x;
    if (e >= Etot) return;
    int s, d;
    if (e < E) { s = ei[e]; d = ei[E + e]; }
    else       { s = e - E; d = s; }
    int pos = atomicAdd(&cursor[d], 1);
    csr[pos] = s;
}

// ---------------------------------------------------------------------------
// Node-parallel fused GATv2 aggregation: one warp per dst node.
// 4-wide software pipeline: 4 outstanding gathers, 4 interleaved score chains.
// ---------------------------------------------------------------------------
__device__ __forceinline__ float lrelu(float x) { return fmaxf(x, 0.2f * x); }

template<int H, bool RELU>
__global__ void __launch_bounds__(256) node_agg_kernel(
    const float* __restrict__ xl, const float* __restrict__ xr,
    const int* __restrict__ row, const int* __restrict__ csr,
    const float* __restrict__ att, const float* __restrict__ bias,
    float* __restrict__ out, int Nn)
{
    int n = (blockIdx.x * blockDim.x + threadIdx.x) >> 5;
    if (n >= Nn) return;
    const int lane = threadIdx.x & 31;

    const float4 b  = ((const float4*)xr)[n * 32 + lane];
    const float4 at = ((const float4*)att)[lane];
    const float4* __restrict__ xl4 = (const float4*)xl;

    const int beg = row[n];
    const int end = row[n + 1];   // deg >= 1 (self loop)

    float4 acc = make_float4(0.f, 0.f, 0.f, 0.f);
    float  den = 0.f;

    float4 cur[4], nxt[4];
#pragma unroll
    for (int j = 0; j < 4; j++)
        cur[j] = xl4[csr[min(beg + j, end - 1)] * 32 + lane];

    int i = beg;
    for (; i + 4 <= end; i += 4) {
        // issue next 4 gathers (overlap with compute below)
#pragma unroll
        for (int j = 0; j < 4; j++)
            nxt[j] = xl4[csr[min(i + 4 + j, end - 1)] * 32 + lane];

        // 4 independent score chains
        float p[4];
#pragma unroll
        for (int j = 0; j < 4; j++) {
            p[j] = lrelu(cur[j].x + b.x) * at.x;
            p[j] = fmaf(lrelu(cur[j].y + b.y), at.y, p[j]);
            p[j] = fmaf(lrelu(cur[j].z + b.z), at.z, p[j]);
            p[j] = fmaf(lrelu(cur[j].w + b.w), at.w, p[j]);
        }
#pragma unroll
        for (int j = 0; j < 4; j++) p[j] += __shfl_xor_sync(0xffffffffu, p[j], 1);
#pragma unroll
        for (int j = 0; j < 4; j++) p[j] += __shfl_xor_sync(0xffffffffu, p[j], 2);
#pragma unroll
        for (int j = 0; j < 4; j++) p[j] += __shfl_xor_sync(0xffffffffu, p[j], 4);
        if (H == 1) {
#pragma unroll
            for (int j = 0; j < 4; j++) p[j] += __shfl_xor_sync(0xffffffffu, p[j], 8);
#pragma unroll
            for (int j = 0; j < 4; j++) p[j] += __shfl_xor_sync(0xffffffffu, p[j], 16);
        }
#pragma unroll
        for (int j = 0; j < 4; j++) {
            float ex = __expf(p[j]);
            den  += ex;
            acc.x = fmaf(cur[j].x, ex, acc.x);
            acc.y = fmaf(cur[j].y, ex, acc.y);
            acc.z = fmaf(cur[j].z, ex, acc.z);
            acc.w = fmaf(cur[j].w, ex, acc.w);
        }
#pragma unroll
        for (int j = 0; j < 4; j++) cur[j] = nxt[j];
    }

    // tail (0..3 edges) — cur[] already holds them (clamped preload)
    for (int j = 0; i + j < end; j++) {
        float4 ac = cur[j];
        float p = lrelu(ac.x + b.x) * at.x;
        p = fmaf(lrelu(ac.y + b.y), at.y, p);
        p = fmaf(lrelu(ac.z + b.z), at.z, p);
        p = fmaf(lrelu(ac.w + b.w), at.w, p);
        p += __shfl_xor_sync(0xffffffffu, p, 1);
        p += __shfl_xor_sync(0xffffffffu, p, 2);
        p += __shfl_xor_sync(0xffffffffu, p, 4);
        if (H == 1) {
            p += __shfl_xor_sync(0xffffffffu, p, 8);
            p += __shfl_xor_sync(0xffffffffu, p, 16);
        }
        float ex = __expf(p);
        den  += ex;
        acc.x = fmaf(ac.x, ex, acc.x);
        acc.y = fmaf(ac.y, ex, acc.y);
        acc.z = fmaf(ac.z, ex, acc.z);
        acc.w = fmaf(ac.w, ex, acc.w);
    }

    const float r  = 1.0f / (den + 1e-16f);
    const float4 bb = ((const float4*)bias)[lane];
    float4 v;
    v.x = fmaf(acc.x, r, bb.x);
    v.y = fmaf(acc.y, r, bb.y);
    v.z = fmaf(acc.z, r, bb.z);
    v.w = fmaf(acc.w, r, bb.w);
    if (RELU) {
        v.x = fmaxf(v.x, 0.f); v.y = fmaxf(v.y, 0.f);
        v.z = fmaxf(v.z, 0.f); v.w = fmaxf(v.w, 0.f);
    }
    ((float4*)out)[n * 32 + lane] = v;
}

// ---------------------------------------------------------------------------
// launch
// ---------------------------------------------------------------------------
extern "C" void kernel_launch(void* const* d_in, const int* in_sizes, int n_in,
                              void* d_out, int out_size)
{
    const int*   ei    = (const int*)d_in[0];
    const float* embed = (const float*)d_in[1];
    const float* Wl1   = (const float*)d_in[2];
    const float* bl1   = (const float*)d_in[3];
    const float* Wr1   = (const float*)d_in[4];
    const float* br1   = (const float*)d_in[5];
    const float* att1  = (const float*)d_in[6];
    const float* b1    = (const float*)d_in[7];
    const float* Wl2   = (const float*)d_in[8];
    const float* bl2   = (const float*)d_in[9];
    const float* Wr2   = (const float*)d_in[10];
    const float* br2   = (const float*)d_in[11];
    const float* att2  = (const float*)d_in[12];
    const float* b2    = (const float*)d_in[13];
    float* out = (float*)d_out;

    const int E    = in_sizes[0] / 2;
    const int Nn   = in_sizes[1] / 128;
    const int Etot = E + Nn;

    float *A, *B, *C;
    int *deg, *row, *cursor, *csr;
    cudaGetSymbolAddress((void**)&A,      g_A);
    cudaGetSymbolAddress((void**)&B,      g_B);
    cudaGetSymbolAddress((void**)&C,      g_C);
    cudaGetSymbolAddress((void**)&deg,    g_deg);
    cudaGetSymbolAddress((void**)&row,    g_row);
    cudaGetSymbolAddress((void**)&cursor, g_cursor);
    cudaGetSymbolAddress((void**)&csr,    g_csr);

    const dim3 gemm_grid((Nn + 63) / 64, 2);
    const int  ethr_blocks  = (Etot + 255) / 256;
    const int  nwarp_blocks = (Nn * 32 + 255) / 256;

    // ---- CSR build (shared by both layers) ----
    cudaMemsetAsync(deg, 0, Nn * sizeof(int));
    hist_kernel<<<ethr_blocks, 256>>>(ei, deg, E, Etot);
    scan_kernel<<<1, 1024>>>(deg, row, cursor, Nn);
    scatter_kernel<<<ethr_blocks, 256>>>(ei, cursor, csr, E, Etot);

    // ---- layer 1 (4 heads x 32 ch) ----
    gemm2_kernel<<<gemm_grid, 256>>>(embed, Wl1, bl1, A, Wr1, br1, B, Nn);
    node_agg_kernel<4, true><<<nwarp_blocks, 256>>>(A, B, row, csr, att1, b1, C, Nn);

    // ---- layer 2 (1 head x 128 ch) ----
    gemm2_kernel<<<gemm_grid, 256>>>(C, Wl2, bl2, A, Wr2, br2, B, Nn);
    node_agg_kernel<1, false><<<nwarp_blocks, 256>>>(A, B, row, csr, att2, b2, out, Nn);
}

// round 8
// speedup vs baseline: 1.2010x; 1.0824x over previous
#include <cuda_runtime.h>
#include <cuda_bf16.h>

#define NMAX 50000
#define EMAX 800000
#define ETOTMAX (EMAX + NMAX)

// Scratch (device globals: allocation-free)
__device__ float g_A[NMAX * 128];     // xl
__device__ float g_B[NMAX * 128];     // xr
__device__ float g_C[NMAX * 128];     // hidden
__device__ int   g_deg[NMAX];
__device__ int   g_row[NMAX + 1];
__device__ int   g_cursor[NMAX];
__device__ int   g_csr[ETOTMAX];      // src ids grouped by dst
__device__ int   g_bsum[256];         // per-block degree sums for scan

// ---------------------------------------------------------------------------
// helpers
// ---------------------------------------------------------------------------
__device__ __forceinline__ unsigned long long pack2(float lo, float hi) {
    unsigned long long r;
    asm("mov.b64 %0, {%1, %2};" : "=l"(r) : "f"(lo), "f"(hi));
    return r;
}
__device__ __forceinline__ void unpack2(unsigned long long v, float& lo, float& hi) {
    asm("mov.b64 {%0, %1}, %2;" : "=f"(lo), "=f"(hi) : "l"(v));
}
__device__ __forceinline__ void fma2(unsigned long long& d, unsigned long long a,
                                     unsigned long long b) {
    asm("fma.rn.f32x2 %0, %1, %2, %0;" : "+l"(d) : "l"(a), "l"(b));
}

// ---------------------------------------------------------------------------
// Persistent dual GEMM, W resident in smem:
//   out = A @ W{0,1} + b{0,1};  64-row tiles, 4x8 micro-tile, f32x2 FMA.
// Dynamic smem: W[128][128] (64KB) + At[16][68] (4.3KB) -> 2 CTAs/SM.
// grid = (148, 2): one full wave; each block loops over tiles.
// ---------------------------------------------------------------------------
#define GP_SMEM (65536 + 16 * 68 * 4)

__global__ void __launch_bounds__(256) gemm_persist_kernel(
    const float* __restrict__ A,
    const float* __restrict__ W0, const float* __restrict__ b0, float* __restrict__ out0,
    const float* __restrict__ W1, const float* __restrict__ b1, float* __restrict__ out1,
    int M, int ntiles)
{
    extern __shared__ float sm[];
    float* Wsm = sm;            // [128][128]
    float* At  = sm + 16384;    // [16][68]

    const float* W    = blockIdx.y ? W1 : W0;
    const float* bias = blockIdx.y ? b1 : b0;
    float*       out  = blockIdx.y ? out1 : out0;

    const int tid = threadIdx.x;

    // load W once per block (coalesced float4)
    for (int i = tid; i < 4096; i += 256)
        ((float4*)Wsm)[i] = ((const float4*)W)[i];

    const int rbase = (tid & 15) << 2;
    const int cbase = (tid >> 4) << 3;
    const int r_ld  = tid >> 2;
    const int q_ld  = tid & 3;

    float4 bb0 = *(const float4*)&bias[cbase];
    float4 bb1 = *(const float4*)&bias[cbase + 4];
    const float bs[8] = {bb0.x, bb0.y, bb0.z, bb0.w, bb1.x, bb1.y, bb1.z, bb1.w};

    for (int tile = blockIdx.x; tile < ntiles; tile += gridDim.x) {
        const int  m0     = tile * 64;
        const bool rvalid = (m0 + r_ld) < M;

        unsigned long long acc2[16];
#pragma unroll
        for (int i = 0; i < 16; i++) acc2[i] = 0ull;

        for (int kk = 0; kk < 128; kk += 16) {
            float4 av = make_float4(0.f, 0.f, 0.f, 0.f);
            if (rvalid) av = *(const float4*)&A[(m0 + r_ld) * 128 + kk + q_ld * 4];

            __syncthreads();   // also orders W load before first compute
            At[(q_ld * 4 + 0) * 68 + r_ld] = av.x;
            At[(q_ld * 4 + 1) * 68 + r_ld] = av.y;
            At[(q_ld * 4 + 2) * 68 + r_ld] = av.z;
            At[(q_ld * 4 + 3) * 68 + r_ld] = av.w;
            __syncthreads();

#pragma unroll
            for (int k = 0; k < 16; k++) {
                float4 a = *(const float4*)&At[k * 68 + rbase];
                ulonglong2 w0 = *(const ulonglong2*)&Wsm[(kk + k) * 128 + cbase];
                ulonglong2 w1 = *(const ulonglong2*)&Wsm[(kk + k) * 128 + cbase + 4];
                unsigned long long wv[4] = {w0.x, w0.y, w1.x, w1.y};
                unsigned long long a2[4];
                a2[0] = pack2(a.x, a.x);
                a2[1] = pack2(a.y, a.y);
                a2[2] = pack2(a.z, a.z);
                a2[3] = pack2(a.w, a.w);
#pragma unroll
                for (int i = 0; i < 4; i++)
#pragma unroll
                    for (int j = 0; j < 4; j++)
                        fma2(acc2[i * 4 + j], a2[i], wv[j]);
            }
        }

#pragma unroll
        for (int i = 0; i < 4; i++) {
            int row = m0 + rbase + i;
            if (row < M) {
                float o[8];
#pragma unroll
                for (int j = 0; j < 4; j++) unpack2(acc2[i * 4 + j], o[j * 2], o[j * 2 + 1]);
                float4 v0 = make_float4(o[0] + bs[0], o[1] + bs[1], o[2] + bs[2], o[3] + bs[3]);
                float4 v1 = make_float4(o[4] + bs[4], o[5] + bs[5], o[6] + bs[6], o[7] + bs[7]);
                *(float4*)&out[row * 128 + cbase]     = v0;
                *(float4*)&out[row * 128 + cbase + 4] = v1;
            }
        }
    }
}

// ---------------------------------------------------------------------------
// CSR build: hist -> 3-phase parallel scan -> scatter
// ---------------------------------------------------------------------------
__global__ void __launch_bounds__(256) hist_kernel(const int* __restrict__ ei,
                                                   int* __restrict__ deg, int E, int Etot)
{
    int e = blockIdx.x * blockDim.x + threadIdx.x;
    if (e >= Etot) return;
    int d = (e < E) ? ei[E + e] : (e - E);
    atomicAdd(&deg[d], 1);
}

__global__ void __launch_bounds__(256) scan1_kernel(const int* __restrict__ deg,
                                                    int* __restrict__ bsum, int Nn)
{
    int i = blockIdx.x * 256 + threadIdx.x;
    int v = (i < Nn) ? deg[i] : 0;
#pragma unroll
    for (int off = 16; off; off >>= 1) v += __shfl_down_sync(0xffffffffu, v, off);
    __shared__ int ws[8];
    if ((threadIdx.x & 31) == 0) ws[threadIdx.x >> 5] = v;
    __syncthreads();
    if (threadIdx.x < 8) {
        int s = ws[threadIdx.x];
#pragma unroll
        for (int off = 4; off; off >>= 1) s += __shfl_down_sync(0xffu, s, off);
        if (threadIdx.x == 0) bsum[blockIdx.x] = s;
    }
}

__global__ void __launch_bounds__(256) scan2_kernel(int* __restrict__ bsum,
                                                    int* __restrict__ row,
                                                    int nb, int Nn, int Etot)
{
    __shared__ int smv[256];
    int t = threadIdx.x;
    int v = (t < nb) ? bsum[t] : 0;
    smv[t] = v;
    __syncthreads();
    for (int off = 1; off < 256; off <<= 1) {
        int u = (t >= off) ? smv[t - off] : 0;
        __syncthreads();
        smv[t] += u;
        __syncthreads();
    }
    if (t < nb) bsum[t] = t ? smv[t - 1] : 0;   // exclusive
    if (t == 0) row[Nn] = Etot;
}

__global__ void __launch_bounds__(256) scan3_kernel(const int* __restrict__ deg,
                                                    const int* __restrict__ bsum,
                                                    int* __restrict__ row,
                                                    int* __restrict__ cursor, int Nn)
{
    int i = blockIdx.x * 256 + threadIdx.x;
    int t = threadIdx.x, lane = t & 31, w = t >> 5;
    int v = (i < Nn) ? deg[i] : 0;
    int s = v;
#pragma unroll
    for (int off = 1; off < 32; off <<= 1) {
        int u = __shfl_up_sync(0xffffffffu, s, off);
        if (lane >= off) s += u;
    }
    __shared__ int wsum[8];
    if (lane == 31) wsum[w] = s;
    __syncthreads();
    if (t < 8) {
        int x = wsum[t];
        int y = x;
#pragma unroll
        for (int off = 1; off < 8; off <<= 1) {
            int u = __shfl_up_sync(0xffu, y, off);
            if (t >= off) y += u;
        }
        wsum[t] = y - x;   // exclusive
    }
    __syncthreads();
    int excl = s - v + wsum[w] + bsum[blockIdx.x];
    if (i < Nn) { row[i] = excl; cursor[i] = excl; }
}

__global__ void __launch_bounds__(256) scatter_kernel(const int* __restrict__ ei,
                                                      int* __restrict__ cursor,
                                                      int* __restrict__ csr, int E, int Etot)
{
    int e = blockIdx.x * blockDim.x + threadIdx.x;
    if (e >= Etot) return;
    int s, d;
    if (e < E) { s = ei[e]; d = ei[E + e]; }
    else       { s = e - E; d = s; }
    int pos = atomicAdd(&cursor[d], 1);
    csr[pos] = s;
}

// ---------------------------------------------------------------------------
// Node-parallel fused GATv2 aggregation: one warp per dst node. (R3 version)
// ---------------------------------------------------------------------------
__device__ __forceinline__ float lrelu(float x) { return fmaxf(x, 0.2f * x); }

template<int H, bool RELU>
__global__ void __launch_bounds__(256) node_agg_kernel(
    const float* __restrict__ xl, const float* __restrict__ xr,
    const int* __restrict__ row, const int* __restrict__ csr,
    const float* __restrict__ att, const float* __restrict__ bias,
    float* __restrict__ out, int Nn)
{
    int n = (blockIdx.x * blockDim.x + threadIdx.x) >> 5;
    if (n >= Nn) return;
    const int lane = threadIdx.x & 31;

    const float4 b  = ((const float4*)xr)[n * 32 + lane];
    const float4 at = ((const float4*)att)[lane];

    const int beg = row[n];
    const int end = row[n + 1];

    float4 acc = make_float4(0.f, 0.f, 0.f, 0.f);
    float  den = 0.f;

    float4 a = ((const float4*)xl)[csr[beg] * 32 + lane];
    for (int i = beg; i < end; i++) {
        float4 ac = a;
        if (i + 1 < end) a = ((const float4*)xl)[csr[i + 1] * 32 + lane];

        float p = lrelu(ac.x + b.x) * at.x;
        p = fmaf(lrelu(ac.y + b.y), at.y, p);
        p = fmaf(lrelu(ac.z + b.z), at.z, p);
        p = fmaf(lrelu(ac.w + b.w), at.w, p);
        p += __shfl_xor_sync(0xffffffffu, p, 1);
        p += __shfl_xor_sync(0xffffffffu, p, 2);
        p += __shfl_xor_sync(0xffffffffu, p, 4);
        if (H == 1) {
            p += __shfl_xor_sync(0xffffffffu, p, 8);
            p += __shfl_xor_sync(0xffffffffu, p, 16);
        }
        float ex = __expf(p);
        den  += ex;
        acc.x = fmaf(ac.x, ex, acc.x);
        acc.y = fmaf(ac.y, ex, acc.y);
        acc.z = fmaf(ac.z, ex, acc.z);
        acc.w = fmaf(ac.w, ex, acc.w);
    }

    const float r  = 1.0f / (den + 1e-16f);
    const float4 bb = ((const float4*)bias)[lane];
    float4 v;
    v.x = fmaf(acc.x, r, bb.x);
    v.y = fmaf(acc.y, r, bb.y);
    v.z = fmaf(acc.z, r, bb.z);
    v.w = fmaf(acc.w, r, bb.w);
    if (RELU) {
        v.x = fmaxf(v.x, 0.f); v.y = fmaxf(v.y, 0.f);
        v.z = fmaxf(v.z, 0.f); v.w = fmaxf(v.w, 0.f);
    }
    ((float4*)out)[n * 32 + lane] = v;
}

// ---------------------------------------------------------------------------
// launch
// ---------------------------------------------------------------------------
extern "C" void kernel_launch(void* const* d_in, const int* in_sizes, int n_in,
                              void* d_out, int out_size)
{
    const int*   ei    = (const int*)d_in[0];
    const float* embed = (const float*)d_in[1];
    const float* Wl1   = (const float*)d_in[2];
    const float* bl1   = (const float*)d_in[3];
    const float* Wr1   = (const float*)d_in[4];
    const float* br1   = (const float*)d_in[5];
    const float* att1  = (const float*)d_in[6];
    const float* b1    = (const float*)d_in[7];
    const float* Wl2   = (const float*)d_in[8];
    const float* bl2   = (const float*)d_in[9];
    const float* Wr2   = (const float*)d_in[10];
    const float* br2   = (const float*)d_in[11];
    const float* att2  = (const float*)d_in[12];
    const float* b2    = (const float*)d_in[13];
    float* out = (float*)d_out;

    const int E    = in_sizes[0] / 2;
    const int Nn   = in_sizes[1] / 128;
    const int Etot = E + Nn;

    float *A, *B, *C;
    int *deg, *row, *cursor, *csr, *bsum;
    cudaGetSymbolAddress((void**)&A,      g_A);
    cudaGetSymbolAddress((void**)&B,      g_B);
    cudaGetSymbolAddress((void**)&C,      g_C);
    cudaGetSymbolAddress((void**)&deg,    g_deg);
    cudaGetSymbolAddress((void**)&row,    g_row);
    cudaGetSymbolAddress((void**)&cursor, g_cursor);
    cudaGetSymbolAddress((void**)&csr,    g_csr);
    cudaGetSymbolAddress((void**)&bsum,   g_bsum);

    cudaFuncSetAttribute(gemm_persist_kernel,
                         cudaFuncAttributeMaxDynamicSharedMemorySize, GP_SMEM);

    const int  ntiles       = (Nn + 63) / 64;
    const dim3 gemm_grid(148, 2);
    const int  ethr_blocks  = (Etot + 255) / 256;
    const int  nwarp_blocks = (Nn * 32 + 255) / 256;
    const int  nscan_blocks = (Nn + 255) / 256;   // 196 <= 256

    // ---- CSR build (shared by both layers) ----
    cudaMemsetAsync(deg, 0, Nn * sizeof(int));
    hist_kernel<<<ethr_blocks, 256>>>(ei, deg, E, Etot);
    scan1_kernel<<<nscan_blocks, 256>>>(deg, bsum, Nn);
    scan2_kernel<<<1, 256>>>(bsum, row, nscan_blocks, Nn, Etot);
    scan3_kernel<<<nscan_blocks, 256>>>(deg, bsum, row, cursor, Nn);
    scatter_kernel<<<ethr_blocks, 256>>>(ei, cursor, csr, E, Etot);

    // ---- layer 1 (4 heads x 32 ch) ----
    gemm_persist_kernel<<<gemm_grid, 256, GP_SMEM>>>(embed, Wl1, bl1, A, Wr1, br1, B, Nn, ntiles);
    node_agg_kernel<4, true><<<nwarp_blocks, 256>>>(A, B, row, csr, att1, b1, C, Nn);

    // ---- layer 2 (1 head x 128 ch) ----
    gemm_persist_kernel<<<gemm_grid, 256, GP_SMEM>>>(C, Wl2, bl2, A, Wr2, br2, B, Nn, ntiles);
    node_agg_kernel<1, false><<<nwarp_blocks, 256>>>(A, B, row, csr, att2, b2, out, Nn);
}

// round 10
// speedup vs baseline: 1.2155x; 1.0121x over previous
#include <cuda_runtime.h>
#include <cuda_bf16.h>

#define NMAX 50000
#define EMAX 800000
#define ETOTMAX (EMAX + NMAX)

// Scratch (device globals: allocation-free; zero-initialized at module load)
__device__ float g_A[NMAX * 128];     // xl
__device__ float g_B[NMAX * 128];     // xr
__device__ float g_C[NMAX * 128];     // hidden
__device__ int   g_deg[NMAX];         // must be zero at call entry (re-zeroed in scan23)
__device__ int   g_row[NMAX + 1];
__device__ int   g_cursor[NMAX];
__device__ int   g_csr[ETOTMAX];      // src ids grouped by dst
__device__ int   g_bsum[256];         // per-block degree sums for scan

// ---------------------------------------------------------------------------
// helpers
// ---------------------------------------------------------------------------
__device__ __forceinline__ unsigned long long pack2(float lo, float hi) {
    unsigned long long r;
    asm("mov.b64 %0, {%1, %2};" : "=l"(r) : "f"(lo), "f"(hi));
    return r;
}
__device__ __forceinline__ void unpack2(unsigned long long v, float& lo, float& hi) {
    asm("mov.b64 {%0, %1}, %2;" : "=f"(lo), "=f"(hi) : "l"(v));
}
__device__ __forceinline__ void fma2(unsigned long long& d, unsigned long long a,
                                     unsigned long long b) {
    asm("fma.rn.f32x2 %0, %1, %2, %0;" : "+l"(d) : "l"(a), "l"(b));
}

// ---------------------------------------------------------------------------
// Dual GEMM: out = A @ W{0,1} + b{0,1}.  128x128 tile, 256 threads,
// 8x8 micro-tile (f32x2). W loaded ONCE per CTA into 64KB smem; A staged
// per-16k chunk into At[16][132] with register double-buffering.
// Dyn smem 72.3KB -> 2 CTAs/SM.
// ---------------------------------------------------------------------------
#define GD_SMEM (65536 + 16 * 132 * 4)

__global__ void __launch_bounds__(256, 2) gemm8_kernel(
    const float* __restrict__ A,
    const float* __restrict__ W0, const float* __restrict__ b0, float* __restrict__ out0,
    const float* __restrict__ W1, const float* __restrict__ b1, float* __restrict__ out1,
    int M)
{
    extern __shared__ float sm[];
    float* Wsm = sm;            // [128][128]
    float* At  = sm + 16384;    // [16][132]

    const float* W    = blockIdx.y ? W1 : W0;
    const float* bias = blockIdx.y ? b1 : b0;
    float*       out  = blockIdx.y ? out1 : out0;

    const int tid = threadIdx.x;
    const int m0  = blockIdx.x * 128;

    // one-time W load (coalesced float4)
    for (int i = tid; i < 4096; i += 256)
        ((float4*)Wsm)[i] = ((const float4*)W)[i];

    // A loader mapping: 2 threads per row; q = k-half (0/1) of a 16-k chunk
    const int  r_ld   = tid >> 1;          // 0..127
    const int  q_ld   = tid & 1;           // 0..1 -> k offset 0 or 8
    const bool rvalid = (m0 + r_ld) < M;
    const float* aptr = A + (long long)(m0 + r_ld) * 128 + q_ld * 8;

    // compute mapping: 16 row-groups x 16 col-groups
    const int ty = tid >> 4;               // row group: rows ty*8..+8
    const int tx = tid & 15;               // col group: cols tx*8..+8

    unsigned long long acc[32];
#pragma unroll
    for (int i = 0; i < 32; i++) acc[i] = 0ull;

    float4 areg[2];
#pragma unroll
    for (int j = 0; j < 2; j++)
        areg[j] = rvalid ? *(const float4*)(aptr + j * 4) : make_float4(0.f, 0.f, 0.f, 0.f);

    for (int c = 0; c < 8; c++) {
        __syncthreads();   // previous chunk consumed (also orders W load on c==0)
        // store staged A chunk transposed: At[k'][row]
#pragma unroll
        for (int j = 0; j < 2; j++) {
            At[(q_ld * 8 + j * 4 + 0) * 132 + r_ld] = areg[j].x;
            At[(q_ld * 8 + j * 4 + 1) * 132 + r_ld] = areg[j].y;
            At[(q_ld * 8 + j * 4 + 2) * 132 + r_ld] = areg[j].z;
            At[(q_ld * 8 + j * 4 + 3) * 132 + r_ld] = areg[j].w;
        }
        __syncthreads();

        // prefetch next chunk
        if (c < 7) {
#pragma unroll
            for (int j = 0; j < 2; j++)
                areg[j] = rvalid ? *(const float4*)(aptr + (c + 1) * 16 + j * 4)
                                 : make_float4(0.f, 0.f, 0.f, 0.f);
        }

#pragma unroll
        for (int k = 0; k < 16; k++) {
            const float4 a0 = *(const float4*)&At[k * 132 + ty * 8];
            const float4 a1 = *(const float4*)&At[k * 132 + ty * 8 + 4];
            const ulonglong2 wa = *(const ulonglong2*)&Wsm[(c * 16 + k) * 128 + tx * 8];
            const ulonglong2 wb = *(const ulonglong2*)&Wsm[(c * 16 + k) * 128 + tx * 8 + 4];
            const unsigned long long wv[4] = {wa.x, wa.y, wb.x, wb.y};
            const float as[8] = {a0.x, a0.y, a0.z, a0.w, a1.x, a1.y, a1.z, a1.w};
#pragma unroll
            for (int i = 0; i < 8; i++) {
                const unsigned long long ai = pack2(as[i], as[i]);
#pragma unroll
                for (int j = 0; j < 4; j++) fma2(acc[i * 4 + j], ai, wv[j]);
            }
        }
    }

    const int cbase = tx * 8;
    float4 bb0 = *(const float4*)&bias[cbase];
    float4 bb1 = *(const float4*)&bias[cbase + 4];
    const float bs[8] = {bb0.x, bb0.y, bb0.z, bb0.w, bb1.x, bb1.y, bb1.z, bb1.w};
#pragma unroll
    for (int i = 0; i < 8; i++) {
        const int row = m0 + ty * 8 + i;
        if (row < M) {
            float o[8];
#pragma unroll
            for (int j = 0; j < 4; j++) unpack2(acc[i * 4 + j], o[j * 2], o[j * 2 + 1]);
            float4 v0 = make_float4(o[0] + bs[0], o[1] + bs[1], o[2] + bs[2], o[3] + bs[3]);
            float4 v1 = make_float4(o[4] + bs[4], o[5] + bs[5], o[6] + bs[6], o[7] + bs[7]);
            *(float4*)&out[(long long)row * 128 + cbase]     = v0;
            *(float4*)&out[(long long)row * 128 + cbase + 4] = v1;
        }
    }
}

// ---------------------------------------------------------------------------
// CSR build: hist -> scan1 -> scan23 (+deg rezero) -> scatter
// ---------------------------------------------------------------------------
__global__ void __launch_bounds__(256) hist_kernel(const int* __restrict__ ei,
                                                   int* __restrict__ deg, int E, int Etot)
{
    int e = blockIdx.x * blockDim.x + threadIdx.x;
    if (e >= Etot) return;
    int d = (e < E) ? ei[E + e] : (e - E);
    atomicAdd(&deg[d], 1);
}

__global__ void __launch_bounds__(256) scan1_kernel(const int* __restrict__ deg,
                                                    int* __restrict__ bsum, int Nn)
{
    int i = blockIdx.x * 256 + threadIdx.x;
    int v = (i < Nn) ? deg[i] : 0;
#pragma unroll
    for (int off = 16; off; off >>= 1) v += __shfl_down_sync(0xffffffffu, v, off);
    __shared__ int ws[8];
    if ((threadIdx.x & 31) == 0) ws[threadIdx.x >> 5] = v;
    __syncthreads();
    if (threadIdx.x < 8) {
        int s = ws[threadIdx.x];
#pragma unroll
        for (int off = 4; off; off >>= 1) s += __shfl_down_sync(0xffu, s, off);
        if (threadIdx.x == 0) bsum[blockIdx.x] = s;
    }
}

// merged scan2+scan3: each block computes sum(bsum[0..bid)) itself, then
// intra-block exclusive prefix; writes row/cursor; re-zeroes deg for the
// next replay (deg is zero at module load, so every call sees deg==0).
__global__ void __launch_bounds__(256) scan23_kernel(int* __restrict__ deg,
                                                     const int* __restrict__ bsum,
                                                     int* __restrict__ row,
                                                     int* __restrict__ cursor,
                                                     int nb, int Nn, int Etot)
{
    const int t = threadIdx.x, lane = t & 31, w = t >> 5;
    const int bid = blockIdx.x;

    // block-wide sum of bsum[0..bid)
    int pre = (t < nb && t < bid) ? bsum[t] : 0;
#pragma unroll
    for (int off = 16; off; off >>= 1) pre += __shfl_down_sync(0xffffffffu, pre, off);
    __shared__ int ws[8];
    if (lane == 0) ws[w] = pre;
    __syncthreads();
    if (t == 0) {
        int s = 0;
#pragma unroll
        for (int j = 0; j < 8; j++) s += ws[j];
        ws[0] = s;
    }
    __syncthreads();
    const int base = ws[0];
    __syncthreads();

    // intra-block exclusive prefix of deg
    const int i = bid * 256 + t;
    const int v = (i < Nn) ? deg[i] : 0;
    int s = v;
#pragma unroll
    for (int off = 1; off < 32; off <<= 1) {
        int u = __shfl_up_sync(0xffffffffu, s, off);
        if (lane >= off) s += u;
    }
    __shared__ int wsum[8];
    if (lane == 31) wsum[w] = s;
    __syncthreads();
    if (t < 8) {
        int x = wsum[t], y = x;
#pragma unroll
        for (int off = 1; off < 8; off <<= 1) {
            int u = __shfl_up_sync(0xffu, y, off);
            if (t >= off) y += u;
        }
        wsum[t] = y - x;
    }
    __syncthreads();
    const int excl = s - v + wsum[w] + base;
    if (i < Nn) {
        row[i]    = excl;
        cursor[i] = excl;
        deg[i]    = 0;          // reset for next call
    }
    if (i == 0) row[Nn] = Etot;
}

__global__ void __launch_bounds__(256) scatter_kernel(const int* __restrict__ ei,
                                                      int* __restrict__ cursor,
                                                      int* __restrict__ csr, int E, int Etot)
{
    int e = blockIdx.x * blockDim.x + threadIdx.x;
    if (e >= Etot) return;
    int s, d;
    if (e < E) { s = ei[e]; d = ei[E + e]; }
    else       { s = e - E; d = s; }
    int pos = atomicAdd(&cursor[d], 1);
    csr[pos] = s;
}

// ---------------------------------------------------------------------------
// Node-parallel fused GATv2 aggregation: one warp per dst node. (R3 version)
// ---------------------------------------------------------------------------
__device__ __forceinline__ float lrelu(float x) { return fmaxf(x, 0.2f * x); }

template<int H, bool RELU>
__global__ void __launch_bounds__(256) node_agg_kernel(
    const float* __restrict__ xl, const float* __restrict__ xr,
    const int* __restrict__ row, const int* __restrict__ csr,
    const float* __restrict__ att, const float* __restrict__ bias,
    float* __restrict__ out, int Nn)
{
    int n = (blockIdx.x * blockDim.x + threadIdx.x) >> 5;
    if (n >= Nn) return;
    const int lane = threadIdx.x & 31;

    const float4 b  = ((const float4*)xr)[n * 32 + lane];
    const float4 at = ((const float4*)att)[lane];

    const int beg = row[n];
    const int end = row[n + 1];

    float4 acc = make_float4(0.f, 0.f, 0.f, 0.f);
    float  den = 0.f;

    float4 a = ((const float4*)xl)[csr[beg] * 32 + lane];
    for (int i = beg; i < end; i++) {
        float4 ac = a;
        if (i + 1 < end) a = ((const float4*)xl)[csr[i + 1] * 32 + lane];

        float p = lrelu(ac.x + b.x) * at.x;
        p = fmaf(lrelu(ac.y + b.y), at.y, p);
        p = fmaf(lrelu(ac.z + b.z), at.z, p);
        p = fmaf(lrelu(ac.w + b.w), at.w, p);
        p += __shfl_xor_sync(0xffffffffu, p, 1);
        p += __shfl_xor_sync(0xffffffffu, p, 2);
        p += __shfl_xor_sync(0xffffffffu, p, 4);
        if (H == 1) {
            p += __shfl_xor_sync(0xffffffffu, p, 8);
            p += __shfl_xor_sync(0xffffffffu, p, 16);
        }
        float ex = __expf(p);
        den  += ex;
        acc.x = fmaf(ac.x, ex, acc.x);
        acc.y = fmaf(ac.y, ex, acc.y);
        acc.z = fmaf(ac.z, ex, acc.z);
        acc.w = fmaf(ac.w, ex, acc.w);
    }

    const float r  = 1.0f / (den + 1e-16f);
    const float4 bb = ((const float4*)bias)[lane];
    float4 v;
    v.x = fmaf(acc.x, r, bb.x);
    v.y = fmaf(acc.y, r, bb.y);
    v.z = fmaf(acc.z, r, bb.z);
    v.w = fmaf(acc.w, r, bb.w);
    if (RELU) {
        v.x = fmaxf(v.x, 0.f); v.y = fmaxf(v.y, 0.f);
        v.z = fmaxf(v.z, 0.f); v.w = fmaxf(v.w, 0.f);
    }
    ((float4*)out)[n * 32 + lane] = v;
}

// ---------------------------------------------------------------------------
// launch
// ---------------------------------------------------------------------------
extern "C" void kernel_launch(void* const* d_in, const int* in_sizes, int n_in,
                              void* d_out, int out_size)
{
    const int*   ei    = (const int*)d_in[0];
    const float* embed = (const float*)d_in[1];
    const float* Wl1   = (const float*)d_in[2];
    const float* bl1   = (const float*)d_in[3];
    const float* Wr1   = (const float*)d_in[4];
    const float* br1   = (const float*)d_in[5];
    const float* att1  = (const float*)d_in[6];
    const float* b1    = (const float*)d_in[7];
    const float* Wl2   = (const float*)d_in[8];
    const float* bl2   = (const float*)d_in[9];
    const float* Wr2   = (const float*)d_in[10];
    const float* br2   = (const float*)d_in[11];
    const float* att2  = (const float*)d_in[12];
    const float* b2    = (const float*)d_in[13];
    float* out = (float*)d_out;

    const int E    = in_sizes[0] / 2;
    const int Nn   = in_sizes[1] / 128;
    const int Etot = E + Nn;

    float *A, *B, *C;
    int *deg, *row, *cursor, *csr, *bsum;
    cudaGetSymbolAddress((void**)&A,      g_A);
    cudaGetSymbolAddress((void**)&B,      g_B);
    cudaGetSymbolAddress((void**)&C,      g_C);
    cudaGetSymbolAddress((void**)&deg,    g_deg);
    cudaGetSymbolAddress((void**)&row,    g_row);
    cudaGetSymbolAddress((void**)&cursor, g_cursor);
    cudaGetSymbolAddress((void**)&csr,    g_csr);
    cudaGetSymbolAddress((void**)&bsum,   g_bsum);

    cudaFuncSetAttribute(gemm8_kernel,
                         cudaFuncAttributeMaxDynamicSharedMemorySize, GD_SMEM);

    const dim3 gemm_grid((Nn + 127) / 128, 2);
    const int  ethr_blocks  = (Etot + 255) / 256;
    const int  nwarp_blocks = (Nn * 32 + 255) / 256;
    const int  nscan_blocks = (Nn + 255) / 256;   // 196 <= 256

    // ---- CSR build (deg assumed zero; re-zeroed in scan23) ----
    hist_kernel<<<ethr_blocks, 256>>>(ei, deg, E, Etot);                       // (1)
    scan1_kernel<<<nscan_blocks, 256>>>(deg, bsum, Nn);                        // (2)
    scan23_kernel<<<nscan_blocks, 256>>>(deg, bsum, row, cursor,
                                         nscan_blocks, Nn, Etot);              // (3)
    scatter_kernel<<<ethr_blocks, 256>>>(ei, cursor, csr, E, Etot);            // (4)

    // ---- layer 1 (4 heads x 32 ch) ----
    gemm8_kernel<<<gemm_grid, 256, GD_SMEM>>>(embed, Wl1, bl1, A, Wr1, br1, B, Nn); // (5)
    node_agg_kernel<4, true><<<nwarp_blocks, 256>>>(A, B, row, csr, att1, b1, C, Nn); // (6) <- ncu captures this
    // ---- layer 2 (1 head x 128 ch) ----
    gemm8_kernel<<<gemm_grid, 256, GD_SMEM>>>(C, Wl2, bl2, A, Wr2, br2, B, Nn);
    node_agg_kernel<1, false><<<nwarp_blocks, 256>>>(A, B, row, csr, att2, b2, out, Nn);
}

// round 12
// speedup vs baseline: 1.2767x; 1.0503x over previous
#include <cuda_runtime.h>
#include <cuda_bf16.h>

#define NMAX 50000
#define EMAX 800000
#define ETOTMAX (EMAX + NMAX)

// Scratch (device globals: allocation-free; zero-initialized at module load)
__device__ float g_A[NMAX * 128];     // xl
__device__ float g_B[NMAX * 128];     // xr
__device__ float g_C[NMAX * 128];     // hidden
__device__ int   g_deg[NMAX];         // must be zero at call entry (re-zeroed in scan23)
__device__ int   g_row[NMAX + 1];
__device__ int   g_cursor[NMAX];
__device__ int   g_csr[ETOTMAX];      // src ids grouped by dst
__device__ int   g_bsum[256];         // per-block degree sums for scan

// ---------------------------------------------------------------------------
// helpers
// ---------------------------------------------------------------------------
__device__ __forceinline__ unsigned long long pack2(float lo, float hi) {
    unsigned long long r;
    asm("mov.b64 %0, {%1, %2};" : "=l"(r) : "f"(lo), "f"(hi));
    return r;
}
__device__ __forceinline__ void unpack2(unsigned long long v, float& lo, float& hi) {
    asm("mov.b64 {%0, %1}, %2;" : "=f"(lo), "=f"(hi) : "l"(v));
}
__device__ __forceinline__ void fma2(unsigned long long& d, unsigned long long a,
                                     unsigned long long b) {
    asm("fma.rn.f32x2 %0, %1, %2, %0;" : "+l"(d) : "l"(a), "l"(b));
}

// ---------------------------------------------------------------------------
// Dual GEMM: out = A @ W{0,1} + b{0,1}.  128x128 tile, 256 threads,
// 8x8 micro-tile (f32x2). W loaded ONCE per CTA into 64KB smem; A staged
// per-16k chunk into At[16][132] with register double-buffering.
// ---------------------------------------------------------------------------
#define GD_SMEM (65536 + 16 * 132 * 4)

__global__ void __launch_bounds__(256, 2) gemm8_kernel(
    const float* __restrict__ A,
    const float* __restrict__ W0, const float* __restrict__ b0, float* __restrict__ out0,
    const float* __restrict__ W1, const float* __restrict__ b1, float* __restrict__ out1,
    int M)
{
    extern __shared__ float sm[];
    float* Wsm = sm;            // [128][128]
    float* At  = sm + 16384;    // [16][132]

    const float* W    = blockIdx.y ? W1 : W0;
    const float* bias = blockIdx.y ? b1 : b0;
    float*       out  = blockIdx.y ? out1 : out0;

    const int tid = threadIdx.x;
    const int m0  = blockIdx.x * 128;

    for (int i = tid; i < 4096; i += 256)
        ((float4*)Wsm)[i] = ((const float4*)W)[i];

    const int  r_ld   = tid >> 1;
    const int  q_ld   = tid & 1;
    const bool rvalid = (m0 + r_ld) < M;
    const float* aptr = A + (long long)(m0 + r_ld) * 128 + q_ld * 8;

    const int ty = tid >> 4;
    const int tx = tid & 15;

    unsigned long long acc[32];
#pragma unroll
    for (int i = 0; i < 32; i++) acc[i] = 0ull;

    float4 areg[2];
#pragma unroll
    for (int j = 0; j < 2; j++)
        areg[j] = rvalid ? *(const float4*)(aptr + j * 4) : make_float4(0.f, 0.f, 0.f, 0.f);

    for (int c = 0; c < 8; c++) {
        __syncthreads();
#pragma unroll
        for (int j = 0; j < 2; j++) {
            At[(q_ld * 8 + j * 4 + 0) * 132 + r_ld] = areg[j].x;
            At[(q_ld * 8 + j * 4 + 1) * 132 + r_ld] = areg[j].y;
            At[(q_ld * 8 + j * 4 + 2) * 132 + r_ld] = areg[j].z;
            At[(q_ld * 8 + j * 4 + 3) * 132 + r_ld] = areg[j].w;
        }
        __syncthreads();

        if (c < 7) {
#pragma unroll
            for (int j = 0; j < 2; j++)
                areg[j] = rvalid ? *(const float4*)(aptr + (c + 1) * 16 + j * 4)
                                 : make_float4(0.f, 0.f, 0.f, 0.f);
        }

#pragma unroll
        for (int k = 0; k < 16; k++) {
            const float4 a0 = *(const float4*)&At[k * 132 + ty * 8];
            const float4 a1 = *(const float4*)&At[k * 132 + ty * 8 + 4];
            const ulonglong2 wa = *(const ulonglong2*)&Wsm[(c * 16 + k) * 128 + tx * 8];
            const ulonglong2 wb = *(const ulonglong2*)&Wsm[(c * 16 + k) * 128 + tx * 8 + 4];
            const unsigned long long wv[4] = {wa.x, wa.y, wb.x, wb.y};
            const float as[8] = {a0.x, a0.y, a0.z, a0.w, a1.x, a1.y, a1.z, a1.w};
#pragma unroll
            for (int i = 0; i < 8; i++) {
                const unsigned long long ai = pack2(as[i], as[i]);
#pragma unroll
                for (int j = 0; j < 4; j++) fma2(acc[i * 4 + j], ai, wv[j]);
            }
        }
    }

    const int cbase = tx * 8;
    float4 bb0 = *(const float4*)&bias[cbase];
    float4 bb1 = *(const float4*)&bias[cbase + 4];
    const float bs[8] = {bb0.x, bb0.y, bb0.z, bb0.w, bb1.x, bb1.y, bb1.z, bb1.w};
#pragma unroll
    for (int i = 0; i < 8; i++) {
        const int row = m0 + ty * 8 + i;
        if (row < M) {
            float o[8];
#pragma unroll
            for (int j = 0; j < 4; j++) unpack2(acc[i * 4 + j], o[j * 2], o[j * 2 + 1]);
            float4 v0 = make_float4(o[0] + bs[0], o[1] + bs[1], o[2] + bs[2], o[3] + bs[3]);
            float4 v1 = make_float4(o[4] + bs[4], o[5] + bs[5], o[6] + bs[6], o[7] + bs[7]);
            *(float4*)&out[(long long)row * 128 + cbase]     = v0;
            *(float4*)&out[(long long)row * 128 + cbase + 4] = v1;
        }
    }
}

// ---------------------------------------------------------------------------
// CSR build: hist -> scan1 -> scan23 (+deg rezero) -> scatter
// ---------------------------------------------------------------------------
__global__ void __launch_bounds__(256) hist_kernel(const int* __restrict__ ei,
                                                   int* __restrict__ deg, int E, int Etot)
{
    int e = blockIdx.x * blockDim.x + threadIdx.x;
    if (e >= Etot) return;
    int d = (e < E) ? ei[E + e] : (e - E);
    atomicAdd(&deg[d], 1);
}

__global__ void __launch_bounds__(256) scan1_kernel(const int* __restrict__ deg,
                                                    int* __restrict__ bsum, int Nn)
{
    int i = blockIdx.x * 256 + threadIdx.x;
    int v = (i < Nn) ? deg[i] : 0;
#pragma unroll
    for (int off = 16; off; off >>= 1) v += __shfl_down_sync(0xffffffffu, v, off);
    __shared__ int ws[8];
    if ((threadIdx.x & 31) == 0) ws[threadIdx.x >> 5] = v;
    __syncthreads();
    if (threadIdx.x < 8) {
        int s = ws[threadIdx.x];
#pragma unroll
        for (int off = 4; off; off >>= 1) s += __shfl_down_sync(0xffu, s, off);
        if (threadIdx.x == 0) bsum[blockIdx.x] = s;
    }
}

__global__ void __launch_bounds__(256) scan23_kernel(int* __restrict__ deg,
                                                     const int* __restrict__ bsum,
                                                     int* __restrict__ row,
                                                     int* __restrict__ cursor,
                                                     int nb, int Nn, int Etot)
{
    const int t = threadIdx.x, lane = t & 31, w = t >> 5;
    const int bid = blockIdx.x;

    int pre = (t < nb && t < bid) ? bsum[t] : 0;
#pragma unroll
    for (int off = 16; off; off >>= 1) pre += __shfl_down_sync(0xffffffffu, pre, off);
    __shared__ int ws[8];
    if (lane == 0) ws[w] = pre;
    __syncthreads();
    if (t == 0) {
        int s = 0;
#pragma unroll
        for (int j = 0; j < 8; j++) s += ws[j];
        ws[0] = s;
    }
    __syncthreads();
    const int base = ws[0];
    __syncthreads();

    const int i = bid * 256 + t;
    const int v = (i < Nn) ? deg[i] : 0;
    int s = v;
#pragma unroll
    for (int off = 1; off < 32; off <<= 1) {
        int u = __shfl_up_sync(0xffffffffu, s, off);
        if (lane >= off) s += u;
    }
    __shared__ int wsum[8];
    if (lane == 31) wsum[w] = s;
    __syncthreads();
    if (t < 8) {
        int x = wsum[t], y = x;
#pragma unroll
        for (int off = 1; off < 8; off <<= 1) {
            int u = __shfl_up_sync(0xffu, y, off);
            if (t >= off) y += u;
        }
        wsum[t] = y - x;
    }
    __syncthreads();
    const int excl = s - v + wsum[w] + base;
    if (i < Nn) {
        row[i]    = excl;
        cursor[i] = excl;
        deg[i]    = 0;
    }
    if (i == 0) row[Nn] = Etot;
}

__global__ void __launch_bounds__(256) scatter_kernel(const int* __restrict__ ei,
                                                      int* __restrict__ cursor,
                                                      int* __restrict__ csr, int E, int Etot)
{
    int e = blockIdx.x * blockDim.x + threadIdx.x;
    if (e >= Etot) return;
    int s, d;
    if (e < E) { s = ei[e]; d = ei[E + e]; }
    else       { s = e - E; d = s; }
    int pos = atomicAdd(&cursor[d], 1);
    csr[pos] = s;
}

// ---------------------------------------------------------------------------
// Node-parallel fused GATv2 aggregation: one warp per dst node.
// ---------------------------------------------------------------------------
__device__ __forceinline__ float lrelu(float x) { return fmaxf(x, 0.2f * x); }

template<int H, bool RELU>
__global__ void __launch_bounds__(256) node_agg_kernel(
    const float* __restrict__ xl, const float* __restrict__ xr,
    const int* __restrict__ row, const int* __restrict__ csr,
    const float* __restrict__ att, const float* __restrict__ bias,
    float* __restrict__ out, int Nn)
{
    int n = (blockIdx.x * blockDim.x + threadIdx.x) >> 5;
    if (n >= Nn) return;
    const int lane = threadIdx.x & 31;

    const float4 b  = ((const float4*)xr)[n * 32 + lane];
    const float4 at = ((const float4*)att)[lane];

    const int beg = row[n];
    const int end = row[n + 1];

    float4 acc = make_float4(0.f, 0.f, 0.f, 0.f);
    float  den = 0.f;

    float4 a = ((const float4*)xl)[csr[beg] * 32 + lane];
    for (int i = beg; i < end; i++) {
        float4 ac = a;
        if (i + 1 < end) a = ((const float4*)xl)[csr[i + 1] * 32 + lane];

        float p = lrelu(ac.x + b.x) * at.x;
        p = fmaf(lrelu(ac.y + b.y), at.y, p);
        p = fmaf(lrelu(ac.z + b.z), at.z, p);
        p = fmaf(lrelu(ac.w + b.w), at.w, p);
        p += __shfl_xor_sync(0xffffffffu, p, 1);
        p += __shfl_xor_sync(0xffffffffu, p, 2);
        p += __shfl_xor_sync(0xffffffffu, p, 4);
        if (H == 1) {
            p += __shfl_xor_sync(0xffffffffu, p, 8);
            p += __shfl_xor_sync(0xffffffffu, p, 16);
        }
        float ex = __expf(p);
        den  += ex;
        acc.x = fmaf(ac.x, ex, acc.x);
        acc.y = fmaf(ac.y, ex, acc.y);
        acc.z = fmaf(ac.z, ex, acc.z);
        acc.w = fmaf(ac.w, ex, acc.w);
    }

    const float r  = 1.0f / (den + 1e-16f);
    const float4 bb = ((const float4*)bias)[lane];
    float4 v;
    v.x = fmaf(acc.x, r, bb.x);
    v.y = fmaf(acc.y, r, bb.y);
    v.z = fmaf(acc.z, r, bb.z);
    v.w = fmaf(acc.w, r, bb.w);
    if (RELU) {
        v.x = fmaxf(v.x, 0.f); v.y = fmaxf(v.y, 0.f);
        v.z = fmaxf(v.z, 0.f); v.w = fmaxf(v.w, 0.f);
    }
    ((float4*)out)[n * 32 + lane] = v;
}

// ---------------------------------------------------------------------------
// launch — CSR chain forked onto a side stream, overlapped with gemm1.
// ---------------------------------------------------------------------------
extern "C" void kernel_launch(void* const* d_in, const int* in_sizes, int n_in,
                              void* d_out, int out_size)
{
    const int*   ei    = (const int*)d_in[0];
    const float* embed = (const float*)d_in[1];
    const float* Wl1   = (const float*)d_in[2];
    const float* bl1   = (const float*)d_in[3];
    const float* Wr1   = (const float*)d_in[4];
    const float* br1   = (const float*)d_in[5];
    const float* att1  = (const float*)d_in[6];
    const float* b1    = (const float*)d_in[7];
    const float* Wl2   = (const float*)d_in[8];
    const float* bl2   = (const float*)d_in[9];
    const float* Wr2   = (const float*)d_in[10];
    const float* br2   = (const float*)d_in[11];
    const float* att2  = (const float*)d_in[12];
    const float* b2    = (const float*)d_in[13];
    float* out = (float*)d_out;

    const int E    = in_sizes[0] / 2;
    const int Nn   = in_sizes[1] / 128;
    const int Etot = E + Nn;

    float *A, *B, *C;
    int *deg, *row, *cursor, *csr, *bsum;
    cudaGetSymbolAddress((void**)&A,      g_A);
    cudaGetSymbolAddress((void**)&B,      g_B);
    cudaGetSymbolAddress((void**)&C,      g_C);
    cudaGetSymbolAddress((void**)&deg,    g_deg);
    cudaGetSymbolAddress((void**)&row,    g_row);
    cudaGetSymbolAddress((void**)&cursor, g_cursor);
    cudaGetSymbolAddress((void**)&csr,    g_csr);
    cudaGetSymbolAddress((void**)&bsum,   g_bsum);

    static cudaStream_t s_side = nullptr;
    static cudaEvent_t  ev_fork = nullptr, ev_join = nullptr;
    if (s_side == nullptr) {
        cudaStreamCreateWithFlags(&s_side, cudaStreamNonBlocking);
        cudaEventCreateWithFlags(&ev_fork, cudaEventDisableTiming);
        cudaEventCreateWithFlags(&ev_join, cudaEventDisableTiming);
        cudaFuncSetAttribute(gemm8_kernel,
                             cudaFuncAttributeMaxDynamicSharedMemorySize, GD_SMEM);
    }

    const dim3 gemm_grid((Nn + 127) / 128, 2);
    const int  ethr_blocks  = (Etot + 255) / 256;
    const int  nwarp_blocks = (Nn * 32 + 255) / 256;
    const int  nscan_blocks = (Nn + 255) / 256;   // 196 <= 256

    // ---- fork: CSR chain on side stream, gemm1 on main stream ----
    cudaEventRecord(ev_fork, 0);
    cudaStreamWaitEvent(s_side, ev_fork, 0);

    hist_kernel<<<ethr_blocks, 256, 0, s_side>>>(ei, deg, E, Etot);
    scan1_kernel<<<nscan_blocks, 256, 0, s_side>>>(deg, bsum, Nn);
    scan23_kernel<<<nscan_blocks, 256, 0, s_side>>>(deg, bsum, row, cursor,
                                                    nscan_blocks, Nn, Etot);
    scatter_kernel<<<ethr_blocks, 256, 0, s_side>>>(ei, cursor, csr, E, Etot);

    gemm8_kernel<<<gemm_grid, 256, GD_SMEM>>>(embed, Wl1, bl1, A, Wr1, br1, B, Nn);

    // ---- join before agg1 ----
    cudaEventRecord(ev_join, s_side);
    cudaStreamWaitEvent(0, ev_join, 0);

    // ---- layer 1 aggregation, then layer 2 ----
    node_agg_kernel<4, true><<<nwarp_blocks, 256>>>(A, B, row, csr, att1, b1, C, Nn);
    gemm8_kernel<<<gemm_grid, 256, GD_SMEM>>>(C, Wl2, bl2, A, Wr2, br2, B, Nn);
    node_agg_kernel<1, false><<<nwarp_blocks, 256>>>(A, B, row, csr, att2, b2, out, Nn);
}